// round 15
// baseline (speedup 1.0000x reference)
#include <cuda_runtime.h>
#include <cuda_bf16.h>
#include <cstdint>

// GraphSAGE 2-layer, N=100000, E=1600000, D=128.
// R15: R14 (tensor-core bf16x3 GEMM, 329.9us) + ISOLATED change: aggregation
// inner loop widened 4 -> 8 gathers in flight (deg~16 -> two clean 8-groups).
// Everything else byte-identical to R14.

#define N_NODES 100000
#define N_EDGES 1600000
#define DFEAT   128
#define SCAN_BLK 1024
#define MAX_SCAN_BLOCKS ((N_NODES + SCAN_BLK - 1) / SCAN_BLK + 1)

// ---------------- scratch (device globals; no allocation allowed) ----------
__device__ int   g_is_i64;
__device__ int   g_src[N_EDGES];
__device__ int   g_dst[N_EDGES];
__device__ int   g_cursor[N_NODES];
__device__ int   g_rowptr[N_NODES + 1];
__device__ int   g_col[N_EDGES];
__device__ int   g_bsum[MAX_SCAN_BLOCKS];
__device__ float g_mean[(size_t)N_NODES * DFEAT];
__device__ float g_h[(size_t)N_NODES * DFEAT];

// ---------------- helpers ---------------------------------------------------
__device__ __forceinline__ int clamp_node(int v, int n) {
    unsigned u = (unsigned)v;
    return (u < (unsigned)n) ? v : 0;
}
__device__ __forceinline__ uint32_t smem_u32(const void* p) {
    uint32_t a;
    asm("{ .reg .u64 t; cvta.to.shared.u64 t, %1; cvt.u32.u64 %0, t; }"
        : "=r"(a) : "l"(p));
    return a;
}

#define LDMX4(r, addr) \
    asm volatile("ldmatrix.sync.aligned.m8n8.x4.shared.b16 {%0,%1,%2,%3}, [%4];" \
        : "=r"((r)[0]), "=r"((r)[1]), "=r"((r)[2]), "=r"((r)[3]) : "r"(addr))
#define LDMX2(r0, r1, addr) \
    asm volatile("ldmatrix.sync.aligned.m8n8.x2.shared.b16 {%0,%1}, [%2];" \
        : "=r"(r0), "=r"(r1) : "r"(addr))
#define MMA4(d, a, b0_, b1_) \
    asm volatile("mma.sync.aligned.m16n8k16.row.col.f32.bf16.bf16.f32 " \
        "{%0,%1,%2,%3}, {%4,%5,%6,%7}, {%8,%9}, {%0,%1,%2,%3};" \
        : "+f"((d)[0]), "+f"((d)[1]), "+f"((d)[2]), "+f"((d)[3]) \
        : "r"((a)[0]), "r"((a)[1]), "r"((a)[2]), "r"((a)[3]), "r"(b0_), "r"(b1_))

// ---------------- edge dtype detect + (extract + degree count) -------------
__global__ void detect_kernel(const int* __restrict__ ew) {
    int flag = 0;
    for (int i = 1; i < 128; i += 2) flag |= ew[i];
    g_is_i64 = (flag == 0) ? 1 : 0;
}

__global__ void convert_count_kernel(const int* __restrict__ ew, int nedges, int nnodes) {
    int e = blockIdx.x * blockDim.x + threadIdx.x;
    if (e >= nedges) return;
    int s, d;
    if (g_is_i64) {
        s = ew[2 * (size_t)e];
        d = ew[2 * ((size_t)nedges + e)];
    } else {
        s = ew[e];
        d = ew[(size_t)nedges + e];
    }
    s = clamp_node(s, nnodes);
    d = clamp_node(d, nnodes);
    g_src[e] = s;
    g_dst[e] = d;
    atomicAdd(&g_cursor[d], 1);
}

__global__ void zero_int_kernel(int* p, int n) {
    int i = blockIdx.x * blockDim.x + threadIdx.x;
    if (i < n) p[i] = 0;
}

// ---------------- parallel scan: 3 phases ----------------------------------
__global__ void __launch_bounds__(SCAN_BLK)
scan_partial_kernel(int n) {
    __shared__ int warp_sums[32];
    int i = blockIdx.x * SCAN_BLK + threadIdx.x;
    int lane = threadIdx.x & 31;
    int wid = threadIdx.x >> 5;
    int v = (i < n) ? g_cursor[i] : 0;
    int x = v;
#pragma unroll
    for (int o = 1; o < 32; o <<= 1) {
        int y = __shfl_up_sync(0xffffffffu, x, o);
        if (lane >= o) x += y;
    }
    if (lane == 31) warp_sums[wid] = x;
    __syncthreads();
    if (wid == 0) {
        int s = warp_sums[lane];
#pragma unroll
        for (int o = 1; o < 32; o <<= 1) {
            int y = __shfl_up_sync(0xffffffffu, s, o);
            if (lane >= o) s += y;
        }
        warp_sums[lane] = s;
    }
    __syncthreads();
    int base = (wid > 0) ? warp_sums[wid - 1] : 0;
    if (i < n) g_rowptr[i] = base + x - v;
    if (threadIdx.x == SCAN_BLK - 1) g_bsum[blockIdx.x] = base + x;
}

__global__ void __launch_bounds__(SCAN_BLK)
scan_bsums_kernel(int nblocks, int n) {
    __shared__ int warp_sums[32];
    int t = threadIdx.x;
    int lane = t & 31;
    int wid = t >> 5;
    int v = (t < nblocks) ? g_bsum[t] : 0;
    int x = v;
#pragma unroll
    for (int o = 1; o < 32; o <<= 1) {
        int y = __shfl_up_sync(0xffffffffu, x, o);
        if (lane >= o) x += y;
    }
    if (lane == 31) warp_sums[wid] = x;
    __syncthreads();
    if (wid == 0) {
        int s = warp_sums[lane];
#pragma unroll
        for (int o = 1; o < 32; o <<= 1) {
            int y = __shfl_up_sync(0xffffffffu, s, o);
            if (lane >= o) s += y;
        }
        warp_sums[lane] = s;
    }
    __syncthreads();
    int base = (wid > 0) ? warp_sums[wid - 1] : 0;
    if (t < nblocks) g_bsum[t] = base + x - v;
    if (t == SCAN_BLK - 1) g_rowptr[n] = base + x;
}

__global__ void __launch_bounds__(SCAN_BLK)
scan_add_kernel(int n) {
    int i = blockIdx.x * SCAN_BLK + threadIdx.x;
    if (i >= n) return;
    g_rowptr[i] += g_bsum[blockIdx.x];
    g_cursor[i] = 0;
}

__global__ void fill_csr_kernel(int nedges) {
    int e = blockIdx.x * blockDim.x + threadIdx.x;
    if (e >= nedges) return;
    int dst = g_dst[e];
    int pos = g_rowptr[dst] + atomicAdd(&g_cursor[dst], 1);
    g_col[pos] = g_src[e];
}

// ---------------- mean aggregation: one warp per node, 8-wide ---------------
__global__ void agg_mean_kernel(const float* __restrict__ feat, int nnodes) {
    int gwarp = (blockIdx.x * blockDim.x + threadIdx.x) >> 5;
    int lane = threadIdx.x & 31;
    if (gwarp >= nnodes) return;

    int start = g_rowptr[gwarp];
    int end = g_rowptr[gwarp + 1];
    float ax = 0.f, ay = 0.f, az = 0.f, aw = 0.f;
    int lane4 = lane * 4;

    for (int base = start; base < end; base += 32) {
        int m = min(32, end - base);
        int sv = (lane < m) ? g_col[base + lane] : 0;
        int kk = 0;
        for (; kk + 8 <= m; kk += 8) {
            int s0 = __shfl_sync(0xffffffffu, sv, kk);
            int s1 = __shfl_sync(0xffffffffu, sv, kk + 1);
            int s2 = __shfl_sync(0xffffffffu, sv, kk + 2);
            int s3 = __shfl_sync(0xffffffffu, sv, kk + 3);
            int s4 = __shfl_sync(0xffffffffu, sv, kk + 4);
            int s5 = __shfl_sync(0xffffffffu, sv, kk + 5);
            int s6 = __shfl_sync(0xffffffffu, sv, kk + 6);
            int s7 = __shfl_sync(0xffffffffu, sv, kk + 7);
            float4 v0 = *reinterpret_cast<const float4*>(feat + (size_t)s0 * DFEAT + lane4);
            float4 v1 = *reinterpret_cast<const float4*>(feat + (size_t)s1 * DFEAT + lane4);
            float4 v2 = *reinterpret_cast<const float4*>(feat + (size_t)s2 * DFEAT + lane4);
            float4 v3 = *reinterpret_cast<const float4*>(feat + (size_t)s3 * DFEAT + lane4);
            float4 v4 = *reinterpret_cast<const float4*>(feat + (size_t)s4 * DFEAT + lane4);
            float4 v5 = *reinterpret_cast<const float4*>(feat + (size_t)s5 * DFEAT + lane4);
            float4 v6 = *reinterpret_cast<const float4*>(feat + (size_t)s6 * DFEAT + lane4);
            float4 v7 = *reinterpret_cast<const float4*>(feat + (size_t)s7 * DFEAT + lane4);
            ax += ((v0.x + v1.x) + (v2.x + v3.x)) + ((v4.x + v5.x) + (v6.x + v7.x));
            ay += ((v0.y + v1.y) + (v2.y + v3.y)) + ((v4.y + v5.y) + (v6.y + v7.y));
            az += ((v0.z + v1.z) + (v2.z + v3.z)) + ((v4.z + v5.z) + (v6.z + v7.z));
            aw += ((v0.w + v1.w) + (v2.w + v3.w)) + ((v4.w + v5.w) + (v6.w + v7.w));
        }
        for (; kk + 4 <= m; kk += 4) {
            int s0 = __shfl_sync(0xffffffffu, sv, kk);
            int s1 = __shfl_sync(0xffffffffu, sv, kk + 1);
            int s2 = __shfl_sync(0xffffffffu, sv, kk + 2);
            int s3 = __shfl_sync(0xffffffffu, sv, kk + 3);
            float4 v0 = *reinterpret_cast<const float4*>(feat + (size_t)s0 * DFEAT + lane4);
            float4 v1 = *reinterpret_cast<const float4*>(feat + (size_t)s1 * DFEAT + lane4);
            float4 v2 = *reinterpret_cast<const float4*>(feat + (size_t)s2 * DFEAT + lane4);
            float4 v3 = *reinterpret_cast<const float4*>(feat + (size_t)s3 * DFEAT + lane4);
            ax += v0.x + v1.x + v2.x + v3.x;
            ay += v0.y + v1.y + v2.y + v3.y;
            az += v0.z + v1.z + v2.z + v3.z;
            aw += v0.w + v1.w + v2.w + v3.w;
        }
        for (; kk < m; ++kk) {
            int s = __shfl_sync(0xffffffffu, sv, kk);
            float4 v = *reinterpret_cast<const float4*>(feat + (size_t)s * DFEAT + lane4);
            ax += v.x; ay += v.y; az += v.z; aw += v.w;
        }
    }
    float inv = 1.f / fmaxf((float)(end - start), 1.f);
    float4 o;
    o.x = ax * inv; o.y = ay * inv; o.z = az * inv; o.w = aw * inv;
    *reinterpret_cast<float4*>(g_mean + (size_t)gwarp * DFEAT + lane4) = o;
}

// ---------------- tensor-core SAGE GEMM (bf16x3 mma.sync) --------------------
#define B_STRIDE 264
#define A_STRIDE 72
#define SB_LO   (128 * B_STRIDE * 2)
#define SA_OFF  (2 * 128 * B_STRIDE * 2)
#define A_MAT   (128 * A_STRIDE * 2)
#define A_BUF   (2 * A_MAT)
#define TC_SMEM (SA_OFF + 2 * A_BUF)
#define GTILE   128

__global__ void __launch_bounds__(512)
sage_gemm_tc(const float* __restrict__ A0,     // mean (k 0..127)
             const float* __restrict__ A1,     // feat (k 128..255)
             const float* __restrict__ Wl,
             const float* __restrict__ Wr,
             const float* __restrict__ bias,
             float* __restrict__ out,
             int nnodes, int relu, int ntiles) {
    extern __shared__ char smem[];
    uint32_t sbase = smem_u32(smem);
    __nv_bfloat16* sb_hi = reinterpret_cast<__nv_bfloat16*>(smem);
    __nv_bfloat16* sb_lo = reinterpret_cast<__nv_bfloat16*>(smem + SB_LO);

    int tid = threadIdx.x;
    int lane = tid & 31;
    int warp = tid >> 5;

    // ---- convert W = [Wl|Wr] to bf16 hi/lo in smem (once per CTA) ----
    for (int idx = tid; idx < 128 * 256; idx += 512) {
        int j = idx >> 8;
        int k = idx & 255;
        float w = (k < 128) ? Wl[j * 128 + k] : Wr[j * 128 + (k - 128)];
        __nv_bfloat16 h = __float2bfloat16(w);
        float lo = w - __bfloat162float(h);
        sb_hi[j * B_STRIDE + k] = h;
        sb_lo[j * B_STRIDE + k] = __float2bfloat16(lo);
    }

    int mi2 = warp & 3;
    int ng = warp >> 2;
    int g = lane >> 2, t4 = lane & 3;

    float breg[4][2];
#pragma unroll
    for (int nt = 0; nt < 4; ++nt) {
        int j = ng * 32 + nt * 8 + t4 * 2;
        breg[nt][0] = bias[j];
        breg[nt][1] = bias[j + 1];
    }

    int arow = lane & 15, ahalf = (lane >> 4) & 1;
    int brow = lane & 7, bhalf = (lane >> 3) & 1;
    uint32_t a_off0 = (uint32_t)((mi2 * 32 + arow) * (A_STRIDE * 2) + ahalf * 16);
    uint32_t a_off1 = (uint32_t)((mi2 * 32 + 16 + arow) * (A_STRIDE * 2) + ahalf * 16);
    uint32_t b_base = sbase + (uint32_t)((ng * 32 + brow) * (B_STRIDE * 2) + bhalf * 16);

    int st_node = tid >> 2;
    int st_q = tid & 3;

    for (int tile = blockIdx.x; tile < ntiles; tile += gridDim.x) {
        int base_node = tile * GTILE;
        int st_gnode = base_node + st_node;
        if (st_gnode >= nnodes) st_gnode = nnodes - 1;
        const float4* a0p = reinterpret_cast<const float4*>(
            A0 + (size_t)st_gnode * DFEAT + st_q * 16);
        const float4* a1p = reinterpret_cast<const float4*>(
            A1 + (size_t)st_gnode * DFEAT + st_q * 16);

        float4 p0 = a0p[0], p1 = a0p[1], p2 = a0p[2], p3 = a0p[3];

        float acc[2][4][4];
#pragma unroll
        for (int mm = 0; mm < 2; ++mm)
#pragma unroll
            for (int nt = 0; nt < 4; ++nt)
#pragma unroll
                for (int q = 0; q < 4; ++q) acc[mm][nt][q] = 0.f;

        for (int c = 0; c < 4; ++c) {
            char* ab = smem + SA_OFF + (c & 1) * A_BUF;
            uint32_t* ah32 = reinterpret_cast<uint32_t*>(
                ab + st_node * (A_STRIDE * 2) + st_q * 32);
            uint32_t* al32 = reinterpret_cast<uint32_t*>(
                ab + A_MAT + st_node * (A_STRIDE * 2) + st_q * 32);
            float f[16] = {p0.x, p0.y, p0.z, p0.w, p1.x, p1.y, p1.z, p1.w,
                           p2.x, p2.y, p2.z, p2.w, p3.x, p3.y, p3.z, p3.w};
#pragma unroll
            for (int i = 0; i < 8; ++i) {
                float x0 = f[2 * i], x1 = f[2 * i + 1];
                __nv_bfloat16 h0 = __float2bfloat16(x0);
                __nv_bfloat16 h1 = __float2bfloat16(x1);
                __nv_bfloat16 l0 = __float2bfloat16(x0 - __bfloat162float(h0));
                __nv_bfloat16 l1 = __float2bfloat16(x1 - __bfloat162float(h1));
                __nv_bfloat162 hv; hv.x = h0; hv.y = h1;
                __nv_bfloat162 lv; lv.x = l0; lv.y = l1;
                ah32[i] = *reinterpret_cast<uint32_t*>(&hv);
                al32[i] = *reinterpret_cast<uint32_t*>(&lv);
            }

            if (c + 1 < 4) {
                const float4* ap = (c + 1 < 2) ? a0p : a1p;
                int qoff = ((c + 1) & 1) * 16;
                p0 = ap[qoff + 0]; p1 = ap[qoff + 1];
                p2 = ap[qoff + 2]; p3 = ap[qoff + 3];
            }
            __syncthreads();

            uint32_t abuf = sbase + SA_OFF + (c & 1) * A_BUF;
            uint32_t kb_b = (uint32_t)(c * 128);
#pragma unroll
            for (int ks = 0; ks < 4; ++ks) {
                uint32_t ak = (uint32_t)(ks * 32);
                uint32_t ah0[4], al0[4], ah1[4], al1[4];
                LDMX4(ah0, abuf + a_off0 + ak);
                LDMX4(al0, abuf + A_MAT + a_off0 + ak);
                LDMX4(ah1, abuf + a_off1 + ak);
                LDMX4(al1, abuf + A_MAT + a_off1 + ak);
                uint32_t kbyte = kb_b + (uint32_t)(ks * 32);
#pragma unroll
                for (int nt = 0; nt < 4; ++nt) {
                    uint32_t ba = b_base + (uint32_t)(nt * 8 * B_STRIDE * 2) + kbyte;
                    uint32_t bh0, bh1, bl0, bl1;
                    LDMX2(bh0, bh1, ba);
                    LDMX2(bl0, bl1, ba + SB_LO);
                    MMA4(acc[0][nt], ah0, bh0, bh1);
                    MMA4(acc[0][nt], ah0, bl0, bl1);
                    MMA4(acc[0][nt], al0, bh0, bh1);
                    MMA4(acc[1][nt], ah1, bh0, bh1);
                    MMA4(acc[1][nt], ah1, bl0, bl1);
                    MMA4(acc[1][nt], al1, bh0, bh1);
                }
            }
        }

#pragma unroll
        for (int mm = 0; mm < 2; ++mm) {
            int ra = base_node + mi2 * 32 + mm * 16 + g;
            int rb = ra + 8;
#pragma unroll
            for (int nt = 0; nt < 4; ++nt) {
                int j = ng * 32 + nt * 8 + t4 * 2;
                float2 o0, o1;
                o0.x = acc[mm][nt][0] + breg[nt][0];
                o0.y = acc[mm][nt][1] + breg[nt][1];
                o1.x = acc[mm][nt][2] + breg[nt][0];
                o1.y = acc[mm][nt][3] + breg[nt][1];
                if (relu) {
                    o0.x = fmaxf(o0.x, 0.f); o0.y = fmaxf(o0.y, 0.f);
                    o1.x = fmaxf(o1.x, 0.f); o1.y = fmaxf(o1.y, 0.f);
                }
                if (ra < nnodes)
                    *reinterpret_cast<float2*>(out + (size_t)ra * DFEAT + j) = o0;
                if (rb < nnodes)
                    *reinterpret_cast<float2*>(out + (size_t)rb * DFEAT + j) = o1;
            }
        }
        __syncthreads();
    }
}

// ---------------- launch ----------------------------------------------------
extern "C" void kernel_launch(void* const* d_in, const int* in_sizes, int n_in,
                              void* d_out, int out_size) {
    const float* x   = (const float*)d_in[0];
    const int*   ew  = (const int*)d_in[1];
    const float* Wl1 = (const float*)d_in[2];
    const float* bl1 = (const float*)d_in[3];
    const float* Wr1 = (const float*)d_in[4];
    const float* Wl2 = (const float*)d_in[5];
    const float* bl2 = (const float*)d_in[6];
    const float* Wr2 = (const float*)d_in[7];
    float*       out = (float*)d_out;

    int n = in_sizes[0] / DFEAT;      // 100000
    int e = in_sizes[1] / 2;          // 1600000

    void *p_mean_v, *p_h_v, *p_cursor_v;
    cudaGetSymbolAddress(&p_mean_v, g_mean);
    cudaGetSymbolAddress(&p_h_v, g_h);
    cudaGetSymbolAddress(&p_cursor_v, g_cursor);
    float* p_mean = (float*)p_mean_v;
    float* p_h = (float*)p_h_v;
    int* p_cursor = (int*)p_cursor_v;

    cudaFuncSetAttribute(sage_gemm_tc,
                         cudaFuncAttributeMaxDynamicSharedMemorySize, TC_SMEM);

    int zb = (n + 255) / 256;
    int eb = (e + 255) / 256;
    int ab = (n + 7) / 8;
    int sb = (n + SCAN_BLK - 1) / SCAN_BLK;
    int ntiles = (n + GTILE - 1) / GTILE;

    // ---- CSR build ----
    detect_kernel<<<1, 1>>>(ew);
    zero_int_kernel<<<zb, 256>>>(p_cursor, n);
    convert_count_kernel<<<eb, 256>>>(ew, e, n);
    scan_partial_kernel<<<sb, SCAN_BLK>>>(n);
    scan_bsums_kernel<<<1, SCAN_BLK>>>(sb, n);
    scan_add_kernel<<<sb, SCAN_BLK>>>(n);
    fill_csr_kernel<<<eb, 256>>>(e);

    // ---- layer 1 ----
    agg_mean_kernel<<<ab, 256>>>(x, n);
    sage_gemm_tc<<<148, 512, TC_SMEM>>>(p_mean, x, Wl1, Wr1, bl1, p_h, n, 1, ntiles);

    // ---- layer 2 ----
    agg_mean_kernel<<<ab, 256>>>(p_h, n);
    sage_gemm_tc<<<148, 512, TC_SMEM>>>(p_mean, p_h, Wl2, Wr2, bl2, out, n, 0, ntiles);
}

// round 16
// speedup vs baseline: 1.1148x; 1.1148x over previous
#include <cuda_runtime.h>
#include <cuda_bf16.h>
#include <cstdint>

// GraphSAGE 2-layer, N=100000, E=1600000, D=128.
// R16: R14 base (tensor-core bf16x3 GEMM, 4-wide agg; 329.9us) + aggregation
// gathers BF16 feature copies (halves the 819MB/layer L2 gather traffic).
// Mean path only is quantized (~1e-4 output error); self path stays fp32.
// GEMM-1 epilogue dual-writes h as fp32 + bf16 so layer 2 needs no convert.

#define N_NODES 100000
#define N_EDGES 1600000
#define DFEAT   128
#define SCAN_BLK 1024
#define MAX_SCAN_BLOCKS ((N_NODES + SCAN_BLK - 1) / SCAN_BLK + 1)

// ---------------- scratch (device globals; no allocation allowed) ----------
__device__ int   g_is_i64;
__device__ int   g_src[N_EDGES];
__device__ int   g_dst[N_EDGES];
__device__ int   g_cursor[N_NODES];
__device__ int   g_rowptr[N_NODES + 1];
__device__ int   g_col[N_EDGES];
__device__ int   g_bsum[MAX_SCAN_BLOCKS];
__device__ float g_mean[(size_t)N_NODES * DFEAT];
__device__ float g_h[(size_t)N_NODES * DFEAT];
__device__ __nv_bfloat16 g_fb[(size_t)N_NODES * DFEAT];   // bf16 gather copy

// ---------------- helpers ---------------------------------------------------
__device__ __forceinline__ int clamp_node(int v, int n) {
    unsigned u = (unsigned)v;
    return (u < (unsigned)n) ? v : 0;
}
__device__ __forceinline__ uint32_t smem_u32(const void* p) {
    uint32_t a;
    asm("{ .reg .u64 t; cvta.to.shared.u64 t, %1; cvt.u32.u64 %0, t; }"
        : "=r"(a) : "l"(p));
    return a;
}

#define LDMX4(r, addr) \
    asm volatile("ldmatrix.sync.aligned.m8n8.x4.shared.b16 {%0,%1,%2,%3}, [%4];" \
        : "=r"((r)[0]), "=r"((r)[1]), "=r"((r)[2]), "=r"((r)[3]) : "r"(addr))
#define LDMX2(r0, r1, addr) \
    asm volatile("ldmatrix.sync.aligned.m8n8.x2.shared.b16 {%0,%1}, [%2];" \
        : "=r"(r0), "=r"(r1) : "r"(addr))
#define MMA4(d, a, b0_, b1_) \
    asm volatile("mma.sync.aligned.m16n8k16.row.col.f32.bf16.bf16.f32 " \
        "{%0,%1,%2,%3}, {%4,%5,%6,%7}, {%8,%9}, {%0,%1,%2,%3};" \
        : "+f"((d)[0]), "+f"((d)[1]), "+f"((d)[2]), "+f"((d)[3]) \
        : "r"((a)[0]), "r"((a)[1]), "r"((a)[2]), "r"((a)[3]), "r"(b0_), "r"(b1_))

// ---------------- edge dtype detect + (extract + degree count) -------------
__global__ void detect_kernel(const int* __restrict__ ew) {
    int flag = 0;
    for (int i = 1; i < 128; i += 2) flag |= ew[i];
    g_is_i64 = (flag == 0) ? 1 : 0;
}

__global__ void convert_count_kernel(const int* __restrict__ ew, int nedges, int nnodes) {
    int e = blockIdx.x * blockDim.x + threadIdx.x;
    if (e >= nedges) return;
    int s, d;
    if (g_is_i64) {
        s = ew[2 * (size_t)e];
        d = ew[2 * ((size_t)nedges + e)];
    } else {
        s = ew[e];
        d = ew[(size_t)nedges + e];
    }
    s = clamp_node(s, nnodes);
    d = clamp_node(d, nnodes);
    g_src[e] = s;
    g_dst[e] = d;
    atomicAdd(&g_cursor[d], 1);
}

__global__ void zero_int_kernel(int* p, int n) {
    int i = blockIdx.x * blockDim.x + threadIdx.x;
    if (i < n) p[i] = 0;
}

// fp32 -> bf16 copy (for layer-1 input gather)
__global__ void to_bf16_kernel(const float* __restrict__ src, size_t nelem) {
    size_t i = ((size_t)blockIdx.x * blockDim.x + threadIdx.x) * 4;
    if (i >= nelem) return;
    float4 v = *reinterpret_cast<const float4*>(src + i);
    __nv_bfloat162 a = __float22bfloat162_rn(make_float2(v.x, v.y));
    __nv_bfloat162 b = __float22bfloat162_rn(make_float2(v.z, v.w));
    uint32_t* dst = reinterpret_cast<uint32_t*>(g_fb + i);
    dst[0] = *reinterpret_cast<uint32_t*>(&a);
    dst[1] = *reinterpret_cast<uint32_t*>(&b);
}

// ---------------- parallel scan: 3 phases ----------------------------------
__global__ void __launch_bounds__(SCAN_BLK)
scan_partial_kernel(int n) {
    __shared__ int warp_sums[32];
    int i = blockIdx.x * SCAN_BLK + threadIdx.x;
    int lane = threadIdx.x & 31;
    int wid = threadIdx.x >> 5;
    int v = (i < n) ? g_cursor[i] : 0;
    int x = v;
#pragma unroll
    for (int o = 1; o < 32; o <<= 1) {
        int y = __shfl_up_sync(0xffffffffu, x, o);
        if (lane >= o) x += y;
    }
    if (lane == 31) warp_sums[wid] = x;
    __syncthreads();
    if (wid == 0) {
        int s = warp_sums[lane];
#pragma unroll
        for (int o = 1; o < 32; o <<= 1) {
            int y = __shfl_up_sync(0xffffffffu, s, o);
            if (lane >= o) s += y;
        }
        warp_sums[lane] = s;
    }
    __syncthreads();
    int base = (wid > 0) ? warp_sums[wid - 1] : 0;
    if (i < n) g_rowptr[i] = base + x - v;
    if (threadIdx.x == SCAN_BLK - 1) g_bsum[blockIdx.x] = base + x;
}

__global__ void __launch_bounds__(SCAN_BLK)
scan_bsums_kernel(int nblocks, int n) {
    __shared__ int warp_sums[32];
    int t = threadIdx.x;
    int lane = t & 31;
    int wid = t >> 5;
    int v = (t < nblocks) ? g_bsum[t] : 0;
    int x = v;
#pragma unroll
    for (int o = 1; o < 32; o <<= 1) {
        int y = __shfl_up_sync(0xffffffffu, x, o);
        if (lane >= o) x += y;
    }
    if (lane == 31) warp_sums[wid] = x;
    __syncthreads();
    if (wid == 0) {
        int s = warp_sums[lane];
#pragma unroll
        for (int o = 1; o < 32; o <<= 1) {
            int y = __shfl_up_sync(0xffffffffu, s, o);
            if (lane >= o) s += y;
        }
        warp_sums[lane] = s;
    }
    __syncthreads();
    int base = (wid > 0) ? warp_sums[wid - 1] : 0;
    if (t < nblocks) g_bsum[t] = base + x - v;
    if (t == SCAN_BLK - 1) g_rowptr[n] = base + x;
}

__global__ void __launch_bounds__(SCAN_BLK)
scan_add_kernel(int n) {
    int i = blockIdx.x * SCAN_BLK + threadIdx.x;
    if (i >= n) return;
    g_rowptr[i] += g_bsum[blockIdx.x];
    g_cursor[i] = 0;
}

__global__ void fill_csr_kernel(int nedges) {
    int e = blockIdx.x * blockDim.x + threadIdx.x;
    if (e >= nedges) return;
    int dst = g_dst[e];
    int pos = g_rowptr[dst] + atomicAdd(&g_cursor[dst], 1);
    g_col[pos] = g_src[e];
}

// ---------------- mean aggregation: one warp per node, bf16 gather ----------
// lane covers features lane*4..+3 via one uint2 (4 bf16 = 8 bytes).
__global__ void agg_mean_kernel(int nnodes) {
    int gwarp = (blockIdx.x * blockDim.x + threadIdx.x) >> 5;
    int lane = threadIdx.x & 31;
    if (gwarp >= nnodes) return;

    int start = g_rowptr[gwarp];
    int end = g_rowptr[gwarp + 1];
    float ax = 0.f, ay = 0.f, az = 0.f, aw = 0.f;
    int lane4 = lane * 4;
    const __nv_bfloat16* fb = g_fb;

    for (int base = start; base < end; base += 32) {
        int m = min(32, end - base);
        int sv = (lane < m) ? g_col[base + lane] : 0;
        int kk = 0;
        for (; kk + 4 <= m; kk += 4) {
            int s0 = __shfl_sync(0xffffffffu, sv, kk);
            int s1 = __shfl_sync(0xffffffffu, sv, kk + 1);
            int s2 = __shfl_sync(0xffffffffu, sv, kk + 2);
            int s3 = __shfl_sync(0xffffffffu, sv, kk + 3);
            uint2 u0 = *reinterpret_cast<const uint2*>(fb + (size_t)s0 * DFEAT + lane4);
            uint2 u1 = *reinterpret_cast<const uint2*>(fb + (size_t)s1 * DFEAT + lane4);
            uint2 u2 = *reinterpret_cast<const uint2*>(fb + (size_t)s2 * DFEAT + lane4);
            uint2 u3 = *reinterpret_cast<const uint2*>(fb + (size_t)s3 * DFEAT + lane4);
            float2 a0 = __bfloat1622float2(*reinterpret_cast<__nv_bfloat162*>(&u0.x));
            float2 b0 = __bfloat1622float2(*reinterpret_cast<__nv_bfloat162*>(&u0.y));
            float2 a1 = __bfloat1622float2(*reinterpret_cast<__nv_bfloat162*>(&u1.x));
            float2 b1 = __bfloat1622float2(*reinterpret_cast<__nv_bfloat162*>(&u1.y));
            float2 a2 = __bfloat1622float2(*reinterpret_cast<__nv_bfloat162*>(&u2.x));
            float2 b2 = __bfloat1622float2(*reinterpret_cast<__nv_bfloat162*>(&u2.y));
            float2 a3 = __bfloat1622float2(*reinterpret_cast<__nv_bfloat162*>(&u3.x));
            float2 b3 = __bfloat1622float2(*reinterpret_cast<__nv_bfloat162*>(&u3.y));
            ax += (a0.x + a1.x) + (a2.x + a3.x);
            ay += (a0.y + a1.y) + (a2.y + a3.y);
            az += (b0.x + b1.x) + (b2.x + b3.x);
            aw += (b0.y + b1.y) + (b2.y + b3.y);
        }
        for (; kk < m; ++kk) {
            int s = __shfl_sync(0xffffffffu, sv, kk);
            uint2 u = *reinterpret_cast<const uint2*>(fb + (size_t)s * DFEAT + lane4);
            float2 a = __bfloat1622float2(*reinterpret_cast<__nv_bfloat162*>(&u.x));
            float2 b = __bfloat1622float2(*reinterpret_cast<__nv_bfloat162*>(&u.y));
            ax += a.x; ay += a.y; az += b.x; aw += b.y;
        }
    }
    float inv = 1.f / fmaxf((float)(end - start), 1.f);
    float4 o;
    o.x = ax * inv; o.y = ay * inv; o.z = az * inv; o.w = aw * inv;
    *reinterpret_cast<float4*>(g_mean + (size_t)gwarp * DFEAT + lane4) = o;
}

// ---------------- tensor-core SAGE GEMM (bf16x3 mma.sync) --------------------
#define B_STRIDE 264
#define A_STRIDE 72
#define SB_LO   (128 * B_STRIDE * 2)
#define SA_OFF  (2 * 128 * B_STRIDE * 2)
#define A_MAT   (128 * A_STRIDE * 2)
#define A_BUF   (2 * A_MAT)
#define TC_SMEM (SA_OFF + 2 * A_BUF)
#define GTILE   128

__global__ void __launch_bounds__(512)
sage_gemm_tc(const float* __restrict__ A0,     // mean (k 0..127)
             const float* __restrict__ A1,     // feat (k 128..255)
             const float* __restrict__ Wl,
             const float* __restrict__ Wr,
             const float* __restrict__ bias,
             float* __restrict__ out,
             __nv_bfloat16* __restrict__ outb,  // optional bf16 copy (or null)
             int nnodes, int relu, int ntiles) {
    extern __shared__ char smem[];
    uint32_t sbase = smem_u32(smem);
    __nv_bfloat16* sb_hi = reinterpret_cast<__nv_bfloat16*>(smem);
    __nv_bfloat16* sb_lo = reinterpret_cast<__nv_bfloat16*>(smem + SB_LO);

    int tid = threadIdx.x;
    int lane = tid & 31;
    int warp = tid >> 5;

    for (int idx = tid; idx < 128 * 256; idx += 512) {
        int j = idx >> 8;
        int k = idx & 255;
        float w = (k < 128) ? Wl[j * 128 + k] : Wr[j * 128 + (k - 128)];
        __nv_bfloat16 h = __float2bfloat16(w);
        float lo = w - __bfloat162float(h);
        sb_hi[j * B_STRIDE + k] = h;
        sb_lo[j * B_STRIDE + k] = __float2bfloat16(lo);
    }

    int mi2 = warp & 3;
    int ng = warp >> 2;
    int g = lane >> 2, t4 = lane & 3;

    float breg[4][2];
#pragma unroll
    for (int nt = 0; nt < 4; ++nt) {
        int j = ng * 32 + nt * 8 + t4 * 2;
        breg[nt][0] = bias[j];
        breg[nt][1] = bias[j + 1];
    }

    int arow = lane & 15, ahalf = (lane >> 4) & 1;
    int brow = lane & 7, bhalf = (lane >> 3) & 1;
    uint32_t a_off0 = (uint32_t)((mi2 * 32 + arow) * (A_STRIDE * 2) + ahalf * 16);
    uint32_t a_off1 = (uint32_t)((mi2 * 32 + 16 + arow) * (A_STRIDE * 2) + ahalf * 16);
    uint32_t b_base = sbase + (uint32_t)((ng * 32 + brow) * (B_STRIDE * 2) + bhalf * 16);

    int st_node = tid >> 2;
    int st_q = tid & 3;

    for (int tile = blockIdx.x; tile < ntiles; tile += gridDim.x) {
        int base_node = tile * GTILE;
        int st_gnode = base_node + st_node;
        if (st_gnode >= nnodes) st_gnode = nnodes - 1;
        const float4* a0p = reinterpret_cast<const float4*>(
            A0 + (size_t)st_gnode * DFEAT + st_q * 16);
        const float4* a1p = reinterpret_cast<const float4*>(
            A1 + (size_t)st_gnode * DFEAT + st_q * 16);

        float4 p0 = a0p[0], p1 = a0p[1], p2 = a0p[2], p3 = a0p[3];

        float acc[2][4][4];
#pragma unroll
        for (int mm = 0; mm < 2; ++mm)
#pragma unroll
            for (int nt = 0; nt < 4; ++nt)
#pragma unroll
                for (int q = 0; q < 4; ++q) acc[mm][nt][q] = 0.f;

        for (int c = 0; c < 4; ++c) {
            char* ab = smem + SA_OFF + (c & 1) * A_BUF;
            uint32_t* ah32 = reinterpret_cast<uint32_t*>(
                ab + st_node * (A_STRIDE * 2) + st_q * 32);
            uint32_t* al32 = reinterpret_cast<uint32_t*>(
                ab + A_MAT + st_node * (A_STRIDE * 2) + st_q * 32);
            float f[16] = {p0.x, p0.y, p0.z, p0.w, p1.x, p1.y, p1.z, p1.w,
                           p2.x, p2.y, p2.z, p2.w, p3.x, p3.y, p3.z, p3.w};
#pragma unroll
            for (int i = 0; i < 8; ++i) {
                float x0 = f[2 * i], x1 = f[2 * i + 1];
                __nv_bfloat16 h0 = __float2bfloat16(x0);
                __nv_bfloat16 h1 = __float2bfloat16(x1);
                __nv_bfloat16 l0 = __float2bfloat16(x0 - __bfloat162float(h0));
                __nv_bfloat16 l1 = __float2bfloat16(x1 - __bfloat162float(h1));
                __nv_bfloat162 hv; hv.x = h0; hv.y = h1;
                __nv_bfloat162 lv; lv.x = l0; lv.y = l1;
                ah32[i] = *reinterpret_cast<uint32_t*>(&hv);
                al32[i] = *reinterpret_cast<uint32_t*>(&lv);
            }

            if (c + 1 < 4) {
                const float4* ap = (c + 1 < 2) ? a0p : a1p;
                int qoff = ((c + 1) & 1) * 16;
                p0 = ap[qoff + 0]; p1 = ap[qoff + 1];
                p2 = ap[qoff + 2]; p3 = ap[qoff + 3];
            }
            __syncthreads();

            uint32_t abuf = sbase + SA_OFF + (c & 1) * A_BUF;
            uint32_t kb_b = (uint32_t)(c * 128);
#pragma unroll
            for (int ks = 0; ks < 4; ++ks) {
                uint32_t ak = (uint32_t)(ks * 32);
                uint32_t ah0[4], al0[4], ah1[4], al1[4];
                LDMX4(ah0, abuf + a_off0 + ak);
                LDMX4(al0, abuf + A_MAT + a_off0 + ak);
                LDMX4(ah1, abuf + a_off1 + ak);
                LDMX4(al1, abuf + A_MAT + a_off1 + ak);
                uint32_t kbyte = kb_b + (uint32_t)(ks * 32);
#pragma unroll
                for (int nt = 0; nt < 4; ++nt) {
                    uint32_t ba = b_base + (uint32_t)(nt * 8 * B_STRIDE * 2) + kbyte;
                    uint32_t bh0, bh1, bl0, bl1;
                    LDMX2(bh0, bh1, ba);
                    LDMX2(bl0, bl1, ba + SB_LO);
                    MMA4(acc[0][nt], ah0, bh0, bh1);
                    MMA4(acc[0][nt], ah0, bl0, bl1);
                    MMA4(acc[0][nt], al0, bh0, bh1);
                    MMA4(acc[1][nt], ah1, bh0, bh1);
                    MMA4(acc[1][nt], ah1, bl0, bl1);
                    MMA4(acc[1][nt], al1, bh0, bh1);
                }
            }
        }

#pragma unroll
        for (int mm = 0; mm < 2; ++mm) {
            int ra = base_node + mi2 * 32 + mm * 16 + g;
            int rb = ra + 8;
#pragma unroll
            for (int nt = 0; nt < 4; ++nt) {
                int j = ng * 32 + nt * 8 + t4 * 2;
                float2 o0, o1;
                o0.x = acc[mm][nt][0] + breg[nt][0];
                o0.y = acc[mm][nt][1] + breg[nt][1];
                o1.x = acc[mm][nt][2] + breg[nt][0];
                o1.y = acc[mm][nt][3] + breg[nt][1];
                if (relu) {
                    o0.x = fmaxf(o0.x, 0.f); o0.y = fmaxf(o0.y, 0.f);
                    o1.x = fmaxf(o1.x, 0.f); o1.y = fmaxf(o1.y, 0.f);
                }
                if (ra < nnodes) {
                    *reinterpret_cast<float2*>(out + (size_t)ra * DFEAT + j) = o0;
                    if (outb) {
                        __nv_bfloat162 b2 = __float22bfloat162_rn(o0);
                        *reinterpret_cast<uint32_t*>(outb + (size_t)ra * DFEAT + j) =
                            *reinterpret_cast<uint32_t*>(&b2);
                    }
                }
                if (rb < nnodes) {
                    *reinterpret_cast<float2*>(out + (size_t)rb * DFEAT + j) = o1;
                    if (outb) {
                        __nv_bfloat162 b2 = __float22bfloat162_rn(o1);
                        *reinterpret_cast<uint32_t*>(outb + (size_t)rb * DFEAT + j) =
                            *reinterpret_cast<uint32_t*>(&b2);
                    }
                }
            }
        }
        __syncthreads();
    }
}

// ---------------- launch ----------------------------------------------------
extern "C" void kernel_launch(void* const* d_in, const int* in_sizes, int n_in,
                              void* d_out, int out_size) {
    const float* x   = (const float*)d_in[0];
    const int*   ew  = (const int*)d_in[1];
    const float* Wl1 = (const float*)d_in[2];
    const float* bl1 = (const float*)d_in[3];
    const float* Wr1 = (const float*)d_in[4];
    const float* Wl2 = (const float*)d_in[5];
    const float* bl2 = (const float*)d_in[6];
    const float* Wr2 = (const float*)d_in[7];
    float*       out = (float*)d_out;

    int n = in_sizes[0] / DFEAT;      // 100000
    int e = in_sizes[1] / 2;          // 1600000

    void *p_mean_v, *p_h_v, *p_cursor_v, *p_fb_v;
    cudaGetSymbolAddress(&p_mean_v, g_mean);
    cudaGetSymbolAddress(&p_h_v, g_h);
    cudaGetSymbolAddress(&p_cursor_v, g_cursor);
    cudaGetSymbolAddress(&p_fb_v, g_fb);
    float* p_mean = (float*)p_mean_v;
    float* p_h = (float*)p_h_v;
    int* p_cursor = (int*)p_cursor_v;
    __nv_bfloat16* p_fb = (__nv_bfloat16*)p_fb_v;

    cudaFuncSetAttribute(sage_gemm_tc,
                         cudaFuncAttributeMaxDynamicSharedMemorySize, TC_SMEM);

    int zb = (n + 255) / 256;
    int eb = (e + 255) / 256;
    int ab = (n + 7) / 8;
    int sb = (n + SCAN_BLK - 1) / SCAN_BLK;
    int ntiles = (n + GTILE - 1) / GTILE;
    size_t nelem = (size_t)n * DFEAT;
    int cb = (int)((nelem / 4 + 255) / 256);

    // ---- CSR build ----
    detect_kernel<<<1, 1>>>(ew);
    zero_int_kernel<<<zb, 256>>>(p_cursor, n);
    convert_count_kernel<<<eb, 256>>>(ew, e, n);
    scan_partial_kernel<<<sb, SCAN_BLK>>>(n);
    scan_bsums_kernel<<<1, SCAN_BLK>>>(sb, n);
    scan_add_kernel<<<sb, SCAN_BLK>>>(n);
    fill_csr_kernel<<<eb, 256>>>(e);

    // ---- layer 1 ----
    to_bf16_kernel<<<cb, 256>>>(x, nelem);
    agg_mean_kernel<<<ab, 256>>>(n);
    sage_gemm_tc<<<148, 512, TC_SMEM>>>(p_mean, x, Wl1, Wr1, bl1,
                                        p_h, p_fb, n, 1, ntiles);

    // ---- layer 2 ----
    agg_mean_kernel<<<ab, 256>>>(n);
    sage_gemm_tc<<<148, 512, TC_SMEM>>>(p_mean, p_h, Wl2, Wr2, bl2,
                                        out, nullptr, n, 0, ntiles);
}

// round 17
// speedup vs baseline: 1.2327x; 1.1058x over previous
#include <cuda_runtime.h>
#include <cuda_fp16.h>
#include <cuda_bf16.h>
#include <cstdint>

// GraphSAGE 2-layer, N=100000, E=1600000, D=128.
// R17: GEMM switched to fp16 x2 scheme — A split fp16 hi+lo (exact to 2^-22),
// B (weights) plain fp16 (dropped term ~2.8e-4, well under the 1e-3 gate).
// 2 MMAs per step (was 3), B smem + ldmatrix halved. Aggregation reverted to
// full fp32 gathers (R14 version) to reserve the error budget for the GEMM.

#define N_NODES 100000
#define N_EDGES 1600000
#define DFEAT   128
#define SCAN_BLK 1024
#define MAX_SCAN_BLOCKS ((N_NODES + SCAN_BLK - 1) / SCAN_BLK + 1)

// ---------------- scratch (device globals; no allocation allowed) ----------
__device__ int   g_is_i64;
__device__ int   g_src[N_EDGES];
__device__ int   g_dst[N_EDGES];
__device__ int   g_cursor[N_NODES];
__device__ int   g_rowptr[N_NODES + 1];
__device__ int   g_col[N_EDGES];
__device__ int   g_bsum[MAX_SCAN_BLOCKS];
__device__ float g_mean[(size_t)N_NODES * DFEAT];
__device__ float g_h[(size_t)N_NODES * DFEAT];

// ---------------- helpers ---------------------------------------------------
__device__ __forceinline__ int clamp_node(int v, int n) {
    unsigned u = (unsigned)v;
    return (u < (unsigned)n) ? v : 0;
}
__device__ __forceinline__ uint32_t smem_u32(const void* p) {
    uint32_t a;
    asm("{ .reg .u64 t; cvta.to.shared.u64 t, %1; cvt.u32.u64 %0, t; }"
        : "=r"(a) : "l"(p));
    return a;
}

#define LDMX4(r, addr) \
    asm volatile("ldmatrix.sync.aligned.m8n8.x4.shared.b16 {%0,%1,%2,%3}, [%4];" \
        : "=r"((r)[0]), "=r"((r)[1]), "=r"((r)[2]), "=r"((r)[3]) : "r"(addr))
#define LDMX2(r0, r1, addr) \
    asm volatile("ldmatrix.sync.aligned.m8n8.x2.shared.b16 {%0,%1}, [%2];" \
        : "=r"(r0), "=r"(r1) : "r"(addr))
#define MMA4H(d, a, b0_, b1_) \
    asm volatile("mma.sync.aligned.m16n8k16.row.col.f32.f16.f16.f32 " \
        "{%0,%1,%2,%3}, {%4,%5,%6,%7}, {%8,%9}, {%0,%1,%2,%3};" \
        : "+f"((d)[0]), "+f"((d)[1]), "+f"((d)[2]), "+f"((d)[3]) \
        : "r"((a)[0]), "r"((a)[1]), "r"((a)[2]), "r"((a)[3]), "r"(b0_), "r"(b1_))

// ---------------- edge dtype detect + (extract + degree count) -------------
__global__ void detect_kernel(const int* __restrict__ ew) {
    int flag = 0;
    for (int i = 1; i < 128; i += 2) flag |= ew[i];
    g_is_i64 = (flag == 0) ? 1 : 0;
}

__global__ void convert_count_kernel(const int* __restrict__ ew, int nedges, int nnodes) {
    int e = blockIdx.x * blockDim.x + threadIdx.x;
    if (e >= nedges) return;
    int s, d;
    if (g_is_i64) {
        s = ew[2 * (size_t)e];
        d = ew[2 * ((size_t)nedges + e)];
    } else {
        s = ew[e];
        d = ew[(size_t)nedges + e];
    }
    s = clamp_node(s, nnodes);
    d = clamp_node(d, nnodes);
    g_src[e] = s;
    g_dst[e] = d;
    atomicAdd(&g_cursor[d], 1);
}

__global__ void zero_int_kernel(int* p, int n) {
    int i = blockIdx.x * blockDim.x + threadIdx.x;
    if (i < n) p[i] = 0;
}

// ---------------- parallel scan: 3 phases ----------------------------------
__global__ void __launch_bounds__(SCAN_BLK)
scan_partial_kernel(int n) {
    __shared__ int warp_sums[32];
    int i = blockIdx.x * SCAN_BLK + threadIdx.x;
    int lane = threadIdx.x & 31;
    int wid = threadIdx.x >> 5;
    int v = (i < n) ? g_cursor[i] : 0;
    int x = v;
#pragma unroll
    for (int o = 1; o < 32; o <<= 1) {
        int y = __shfl_up_sync(0xffffffffu, x, o);
        if (lane >= o) x += y;
    }
    if (lane == 31) warp_sums[wid] = x;
    __syncthreads();
    if (wid == 0) {
        int s = warp_sums[lane];
#pragma unroll
        for (int o = 1; o < 32; o <<= 1) {
            int y = __shfl_up_sync(0xffffffffu, s, o);
            if (lane >= o) s += y;
        }
        warp_sums[lane] = s;
    }
    __syncthreads();
    int base = (wid > 0) ? warp_sums[wid - 1] : 0;
    if (i < n) g_rowptr[i] = base + x - v;
    if (threadIdx.x == SCAN_BLK - 1) g_bsum[blockIdx.x] = base + x;
}

__global__ void __launch_bounds__(SCAN_BLK)
scan_bsums_kernel(int nblocks, int n) {
    __shared__ int warp_sums[32];
    int t = threadIdx.x;
    int lane = t & 31;
    int wid = t >> 5;
    int v = (t < nblocks) ? g_bsum[t] : 0;
    int x = v;
#pragma unroll
    for (int o = 1; o < 32; o <<= 1) {
        int y = __shfl_up_sync(0xffffffffu, x, o);
        if (lane >= o) x += y;
    }
    if (lane == 31) warp_sums[wid] = x;
    __syncthreads();
    if (wid == 0) {
        int s = warp_sums[lane];
#pragma unroll
        for (int o = 1; o < 32; o <<= 1) {
            int y = __shfl_up_sync(0xffffffffu, s, o);
            if (lane >= o) s += y;
        }
        warp_sums[lane] = s;
    }
    __syncthreads();
    int base = (wid > 0) ? warp_sums[wid - 1] : 0;
    if (t < nblocks) g_bsum[t] = base + x - v;
    if (t == SCAN_BLK - 1) g_rowptr[n] = base + x;
}

__global__ void __launch_bounds__(SCAN_BLK)
scan_add_kernel(int n) {
    int i = blockIdx.x * SCAN_BLK + threadIdx.x;
    if (i >= n) return;
    g_rowptr[i] += g_bsum[blockIdx.x];
    g_cursor[i] = 0;
}

__global__ void fill_csr_kernel(int nedges) {
    int e = blockIdx.x * blockDim.x + threadIdx.x;
    if (e >= nedges) return;
    int dst = g_dst[e];
    int pos = g_rowptr[dst] + atomicAdd(&g_cursor[dst], 1);
    g_col[pos] = g_src[e];
}

// ---------------- mean aggregation: one warp per node (R14 fp32) ------------
__global__ void agg_mean_kernel(const float* __restrict__ feat, int nnodes) {
    int gwarp = (blockIdx.x * blockDim.x + threadIdx.x) >> 5;
    int lane = threadIdx.x & 31;
    if (gwarp >= nnodes) return;

    int start = g_rowptr[gwarp];
    int end = g_rowptr[gwarp + 1];
    float ax = 0.f, ay = 0.f, az = 0.f, aw = 0.f;
    int lane4 = lane * 4;

    for (int base = start; base < end; base += 32) {
        int m = min(32, end - base);
        int sv = (lane < m) ? g_col[base + lane] : 0;
        int kk = 0;
        for (; kk + 4 <= m; kk += 4) {
            int s0 = __shfl_sync(0xffffffffu, sv, kk);
            int s1 = __shfl_sync(0xffffffffu, sv, kk + 1);
            int s2 = __shfl_sync(0xffffffffu, sv, kk + 2);
            int s3 = __shfl_sync(0xffffffffu, sv, kk + 3);
            float4 v0 = *reinterpret_cast<const float4*>(feat + (size_t)s0 * DFEAT + lane4);
            float4 v1 = *reinterpret_cast<const float4*>(feat + (size_t)s1 * DFEAT + lane4);
            float4 v2 = *reinterpret_cast<const float4*>(feat + (size_t)s2 * DFEAT + lane4);
            float4 v3 = *reinterpret_cast<const float4*>(feat + (size_t)s3 * DFEAT + lane4);
            ax += v0.x + v1.x + v2.x + v3.x;
            ay += v0.y + v1.y + v2.y + v3.y;
            az += v0.z + v1.z + v2.z + v3.z;
            aw += v0.w + v1.w + v2.w + v3.w;
        }
        for (; kk < m; ++kk) {
            int s = __shfl_sync(0xffffffffu, sv, kk);
            float4 v = *reinterpret_cast<const float4*>(feat + (size_t)s * DFEAT + lane4);
            ax += v.x; ay += v.y; az += v.z; aw += v.w;
        }
    }
    float inv = 1.f / fmaxf((float)(end - start), 1.f);
    float4 o;
    o.x = ax * inv; o.y = ay * inv; o.z = az * inv; o.w = aw * inv;
    *reinterpret_cast<float4*>(g_mean + (size_t)gwarp * DFEAT + lane4) = o;
}

// ---------------- tensor-core SAGE GEMM (fp16 x2 mma.sync) -------------------
// out[n][j] = sum_k A[n][k]*B[j][k] + b[j]; A = [mean|feat] (K=256) split
// fp16 hi+lo; B = [Wl|Wr] plain fp16. d = A_hi*B + A_lo*B (2 MMAs/step).
#define B_STRIDE 264                           // fp16 elems per B row, padded
#define A_STRIDE 72                            // fp16 elems per A row chunk, padded
#define SB_SZ   (128 * B_STRIDE * 2)           // 67584 (single fp16 B)
#define SA_OFF  SB_SZ
#define A_MAT   (128 * A_STRIDE * 2)           // 18432
#define A_BUF   (2 * A_MAT)                    // hi + lo
#define TC_SMEM (SA_OFF + 2 * A_BUF)           // 141312
#define GTILE   128

__global__ void __launch_bounds__(512)
sage_gemm_tc(const float* __restrict__ A0,     // mean (k 0..127)
             const float* __restrict__ A1,     // feat (k 128..255)
             const float* __restrict__ Wl,
             const float* __restrict__ Wr,
             const float* __restrict__ bias,
             float* __restrict__ out,
             int nnodes, int relu, int ntiles) {
    extern __shared__ char smem[];
    uint32_t sbase = smem_u32(smem);
    __half* sb = reinterpret_cast<__half*>(smem);

    int tid = threadIdx.x;
    int lane = tid & 31;
    int warp = tid >> 5;

    // ---- convert W = [Wl|Wr] to fp16 in smem (once per CTA) ----
    for (int idx = tid; idx < 128 * 256; idx += 512) {
        int j = idx >> 8;
        int k = idx & 255;
        float w = (k < 128) ? Wl[j * 128 + k] : Wr[j * 128 + (k - 128)];
        sb[j * B_STRIDE + k] = __float2half_rn(w);
    }

    int mi2 = warp & 3;
    int ng = warp >> 2;
    int g = lane >> 2, t4 = lane & 3;

    float breg[4][2];
#pragma unroll
    for (int nt = 0; nt < 4; ++nt) {
        int j = ng * 32 + nt * 8 + t4 * 2;
        breg[nt][0] = bias[j];
        breg[nt][1] = bias[j + 1];
    }

    int arow = lane & 15, ahalf = (lane >> 4) & 1;
    int brow = lane & 7, bhalf = (lane >> 3) & 1;
    uint32_t a_off0 = (uint32_t)((mi2 * 32 + arow) * (A_STRIDE * 2) + ahalf * 16);
    uint32_t a_off1 = (uint32_t)((mi2 * 32 + 16 + arow) * (A_STRIDE * 2) + ahalf * 16);
    uint32_t b_base = sbase + (uint32_t)((ng * 32 + brow) * (B_STRIDE * 2) + bhalf * 16);

    int st_node = tid >> 2;
    int st_q = tid & 3;

    for (int tile = blockIdx.x; tile < ntiles; tile += gridDim.x) {
        int base_node = tile * GTILE;
        int st_gnode = base_node + st_node;
        if (st_gnode >= nnodes) st_gnode = nnodes - 1;
        const float4* a0p = reinterpret_cast<const float4*>(
            A0 + (size_t)st_gnode * DFEAT + st_q * 16);
        const float4* a1p = reinterpret_cast<const float4*>(
            A1 + (size_t)st_gnode * DFEAT + st_q * 16);

        float4 p0 = a0p[0], p1 = a0p[1], p2 = a0p[2], p3 = a0p[3];

        float acc[2][4][4];
#pragma unroll
        for (int mm = 0; mm < 2; ++mm)
#pragma unroll
            for (int nt = 0; nt < 4; ++nt)
#pragma unroll
                for (int q = 0; q < 4; ++q) acc[mm][nt][q] = 0.f;

        for (int c = 0; c < 4; ++c) {
            // ---- stage chunk c as fp16 hi/lo ----
            char* ab = smem + SA_OFF + (c & 1) * A_BUF;
            uint32_t* ah32 = reinterpret_cast<uint32_t*>(
                ab + st_node * (A_STRIDE * 2) + st_q * 32);
            uint32_t* al32 = reinterpret_cast<uint32_t*>(
                ab + A_MAT + st_node * (A_STRIDE * 2) + st_q * 32);
            float f[16] = {p0.x, p0.y, p0.z, p0.w, p1.x, p1.y, p1.z, p1.w,
                           p2.x, p2.y, p2.z, p2.w, p3.x, p3.y, p3.z, p3.w};
#pragma unroll
            for (int i = 0; i < 8; ++i) {
                float x0 = f[2 * i], x1 = f[2 * i + 1];
                __half h0 = __float2half_rn(x0);
                __half h1 = __float2half_rn(x1);
                __half l0 = __float2half_rn(x0 - __half2float(h0));
                __half l1 = __float2half_rn(x1 - __half2float(h1));
                __half2 hv; hv.x = h0; hv.y = h1;
                __half2 lv; lv.x = l0; lv.y = l1;
                ah32[i] = *reinterpret_cast<uint32_t*>(&hv);
                al32[i] = *reinterpret_cast<uint32_t*>(&lv);
            }

            if (c + 1 < 4) {
                const float4* ap = (c + 1 < 2) ? a0p : a1p;
                int qoff = ((c + 1) & 1) * 16;
                p0 = ap[qoff + 0]; p1 = ap[qoff + 1];
                p2 = ap[qoff + 2]; p3 = ap[qoff + 3];
            }
            __syncthreads();

            uint32_t abuf = sbase + SA_OFF + (c & 1) * A_BUF;
            uint32_t kb_b = (uint32_t)(c * 128);
#pragma unroll
            for (int ks = 0; ks < 4; ++ks) {
                uint32_t ak = (uint32_t)(ks * 32);
                uint32_t ah0[4], al0[4], ah1[4], al1[4];
                LDMX4(ah0, abuf + a_off0 + ak);
                LDMX4(al0, abuf + A_MAT + a_off0 + ak);
                LDMX4(ah1, abuf + a_off1 + ak);
                LDMX4(al1, abuf + A_MAT + a_off1 + ak);
                uint32_t kbyte = kb_b + (uint32_t)(ks * 32);
#pragma unroll
                for (int nt = 0; nt < 4; ++nt) {
                    uint32_t ba = b_base + (uint32_t)(nt * 8 * B_STRIDE * 2) + kbyte;
                    uint32_t b0, b1;
                    LDMX2(b0, b1, ba);
                    MMA4H(acc[0][nt], ah0, b0, b1);
                    MMA4H(acc[0][nt], al0, b0, b1);
                    MMA4H(acc[1][nt], ah1, b0, b1);
                    MMA4H(acc[1][nt], al1, b0, b1);
                }
            }
        }

#pragma unroll
        for (int mm = 0; mm < 2; ++mm) {
            int ra = base_node + mi2 * 32 + mm * 16 + g;
            int rb = ra + 8;
#pragma unroll
            for (int nt = 0; nt < 4; ++nt) {
                int j = ng * 32 + nt * 8 + t4 * 2;
                float2 o0, o1;
                o0.x = acc[mm][nt][0] + breg[nt][0];
                o0.y = acc[mm][nt][1] + breg[nt][1];
                o1.x = acc[mm][nt][2] + breg[nt][0];
                o1.y = acc[mm][nt][3] + breg[nt][1];
                if (relu) {
                    o0.x = fmaxf(o0.x, 0.f); o0.y = fmaxf(o0.y, 0.f);
                    o1.x = fmaxf(o1.x, 0.f); o1.y = fmaxf(o1.y, 0.f);
                }
                if (ra < nnodes)
                    *reinterpret_cast<float2*>(out + (size_t)ra * DFEAT + j) = o0;
                if (rb < nnodes)
                    *reinterpret_cast<float2*>(out + (size_t)rb * DFEAT + j) = o1;
            }
        }
        __syncthreads();
    }
}

// ---------------- launch ----------------------------------------------------
extern "C" void kernel_launch(void* const* d_in, const int* in_sizes, int n_in,
                              void* d_out, int out_size) {
    const float* x   = (const float*)d_in[0];
    const int*   ew  = (const int*)d_in[1];
    const float* Wl1 = (const float*)d_in[2];
    const float* bl1 = (const float*)d_in[3];
    const float* Wr1 = (const float*)d_in[4];
    const float* Wl2 = (const float*)d_in[5];
    const float* bl2 = (const float*)d_in[6];
    const float* Wr2 = (const float*)d_in[7];
    float*       out = (float*)d_out;

    int n = in_sizes[0] / DFEAT;      // 100000
    int e = in_sizes[1] / 2;          // 1600000

    void *p_mean_v, *p_h_v, *p_cursor_v;
    cudaGetSymbolAddress(&p_mean_v, g_mean);
    cudaGetSymbolAddress(&p_h_v, g_h);
    cudaGetSymbolAddress(&p_cursor_v, g_cursor);
    float* p_mean = (float*)p_mean_v;
    float* p_h = (float*)p_h_v;
    int* p_cursor = (int*)p_cursor_v;

    cudaFuncSetAttribute(sage_gemm_tc,
                         cudaFuncAttributeMaxDynamicSharedMemorySize, TC_SMEM);

    int zb = (n + 255) / 256;
    int eb = (e + 255) / 256;
    int ab = (n + 7) / 8;
    int sb = (n + SCAN_BLK - 1) / SCAN_BLK;
    int ntiles = (n + GTILE - 1) / GTILE;

    // ---- CSR build ----
    detect_kernel<<<1, 1>>>(ew);
    zero_int_kernel<<<zb, 256>>>(p_cursor, n);
    convert_count_kernel<<<eb, 256>>>(ew, e, n);
    scan_partial_kernel<<<sb, SCAN_BLK>>>(n);
    scan_bsums_kernel<<<1, SCAN_BLK>>>(sb, n);
    scan_add_kernel<<<sb, SCAN_BLK>>>(n);
    fill_csr_kernel<<<eb, 256>>>(e);

    // ---- layer 1 ----
    agg_mean_kernel<<<ab, 256>>>(x, n);
    sage_gemm_tc<<<148, 512, TC_SMEM>>>(p_mean, x, Wl1, Wr1, bl1, p_h, n, 1, ntiles);

    // ---- layer 2 ----
    agg_mean_kernel<<<ab, 256>>>(p_h, n);
    sage_gemm_tc<<<148, 512, TC_SMEM>>>(p_mean, p_h, Wl2, Wr2, bl2, out, n, 0, ntiles);
}